// round 5
// baseline (speedup 1.0000x reference)
#include <cuda_runtime.h>
#include <cuda_bf16.h>
#include <math_constants.h>

typedef unsigned long long ull;
#define FULLMASK 0xffffffffu
#define NEG_INF (-CUDART_INF_F)

// ---------------- scratch ----------------
__device__ float g_S[16*32*8192];     // scores [b][r][n]
__device__ float g_alpha[64*8192];    // [bt][n]
__device__ float g_part[512];         // partial alpha sums [bt*8+slice]
__device__ float g_G[32*512];
__device__ float g_A[32];
__device__ float g_query[4*512];
__device__ float g_qp[4*512];
__device__ float g_M[512], g_Z[512];
__device__ int   g_sel[64*64];
__device__ float g_w[64*64];
__device__ int   g_cnt[64];
__device__ int   g_mask_mode;

// ---------------- helpers ----------------
__device__ __forceinline__ ull ffma2(ull a, ull b, ull c){
  ull d; asm("fma.rn.f32x2 %0, %1, %2, %3;" : "=l"(d) : "l"(a), "l"(b), "l"(c)); return d;
}
__device__ __forceinline__ ull fadd2(ull a, ull b){
  ull d; asm("add.rn.f32x2 %0, %1, %2;" : "=l"(d) : "l"(a), "l"(b)); return d;
}
__device__ __forceinline__ float2 unpack2(ull v){
  float2 r; asm("mov.b64 {%0, %1}, %2;" : "=f"(r.x), "=f"(r.y) : "l"(v)); return r;
}
__device__ __forceinline__ float wredsum(float v){
  #pragma unroll
  for(int o=16;o;o>>=1) v += __shfl_xor_sync(FULLMASK, v, o);
  return v;
}
__device__ __forceinline__ bool mask_at(const void* m, int idx, int mode){
  if(mode==0) return ((const unsigned char*)m)[idx]!=0;
  if(mode==1) return ((const int*)m)[idx]!=0;
  if(mode==2) return ((const float*)m)[idx]!=0.f;
  return (((const unsigned short*)m)[idx]&0x7fff)!=0;
}

// ---------------- Kd: mask dtype detection ----------------
__global__ void kdetect(const unsigned char* m){
  __shared__ int f[2];
  if(threadIdx.x<2) f[threadIdx.x]=0;
  __syncthreads();
  int gt1=0, nz1=0;
  for(int i=threadIdx.x;i<65536;i+=256){
    unsigned char c=m[i];
    if(c>1) gt1=1;
    if(c && ((i&3)==1)) nz1=1;
  }
  if(gt1) atomicOr(&f[0],1);
  if(nz1) atomicOr(&f[1],1);
  __syncthreads();
  if(threadIdx.x==0){
    int mode;
    if(!f[0]) mode = f[1] ? 0 : 1;   // u8 bool vs int32
    else      mode = f[1] ? 3 : 2;   // bf16 vs f32
    g_mask_mode = mode;
  }
}

// ---------------- K0: query = LN(q)/tau (1 block, 128 thr) ----------------
__global__ void k0(const float* q, const float* qg, const float* qb, const float* logtau){
  int warp = threadIdx.x>>5, lane = threadIdx.x&31;   // warp = t
  float tau = fminf(fmaxf(__expf(logtau[0]), 0.1f), 10.f);
  float inv_tau = 1.f/tau;
  const float4* qr = (const float4*)(q + warp*512);
  float4 x[4]; float s=0.f, ss=0.f;
  #pragma unroll
  for(int j=0;j<4;j++){
    x[j]=qr[lane+32*j];
    s += x[j].x+x[j].y+x[j].z+x[j].w;
    ss += x[j].x*x[j].x + x[j].y*x[j].y + x[j].z*x[j].z + x[j].w*x[j].w;
  }
  s = wredsum(s); ss = wredsum(ss);
  float m = s*(1.f/512.f);
  float rstd = rsqrtf(ss*(1.f/512.f) - m*m + 1e-5f);
  #pragma unroll
  for(int j=0;j<4;j++){
    int d0=(lane+32*j)*4;
    float v[4]={x[j].x,x[j].y,x[j].z,x[j].w};
    #pragma unroll
    for(int c=0;c<4;c++){
      int d=d0+c;
      g_query[warp*512+d] = ((v[c]-m)*rstd*qg[d] + qb[d]) * inv_tau;
    }
  }
}

// ---------------- K1: qp = query @ wq^T + bq (64 blocks, 256 thr) ----------------
__global__ void k1(const float* W, const float* bias){
  int w = blockIdx.x*8 + (threadIdx.x>>5);
  int lane = threadIdx.x&31;
  #pragma unroll
  for(int qq=0;qq<4;qq++){
    int p = w*4+qq;
    int t = p>>9, o = p&511;
    const float4* qr = (const float4*)(g_query + t*512);
    const float4* wr = (const float4*)(W + (size_t)o*512);
    float a=0.f;
    #pragma unroll
    for(int j=0;j<4;j++){
      float4 A=qr[lane+32*j], B=wr[lane+32*j];
      a += A.x*B.x + A.y*B.y + A.z*B.z + A.w*B.w;
    }
    a = wredsum(a);
    if(lane==0) g_qp[t*512+o] = a + bias[o];
  }
}

// ---------------- K2: G[r][d], A[r] (32 blocks, 256 thr) ----------------
__global__ void k2(const float* W, const float* preg){
  __shared__ float qv[64];
  __shared__ float red[8];
  int r = blockIdx.x, t = r>>3, h = r&7, tid = threadIdx.x;
  if(tid<64) qv[tid] = g_qp[t*512 + h*64 + tid];
  __syncthreads();
  float la=0.f;
  #pragma unroll
  for(int rep=0;rep<2;rep++){
    int d = tid + rep*256;
    const float* base = W + (size_t)(512 + h*64)*512 + d;
    float acc=0.f;
    #pragma unroll 8
    for(int j=0;j<64;j++) acc += qv[j]*base[(size_t)j*512];
    float gval = preg[d]*acc*0.125f;   // fold 1/sqrt(64)
    g_G[r*512+d] = gval;
    la += gval;
  }
  float v = wredsum(la);
  if((tid&31)==0) red[tid>>5]=v;
  __syncthreads();
  if(tid==0){
    float a=0.f;
    #pragma unroll
    for(int w2=0;w2<8;w2++) a+=red[w2];
    g_A[r]=a;
  }
}

// ---------------- K3: main streaming pass (512 blocks x 256 thr) ----------------
__global__ void __launch_bounds__(256) k3(const float* tokens){
  __shared__ float Gc[32*32];          // G chunk [r][k]
  __shared__ float As[32];
  __shared__ float xs[8][32*36];       // per-warp tile, stride 36
  int tid=threadIdx.x, warp=tid>>5, lane=tid&31;
  if(tid<32) As[tid]=g_A[tid];
  int tok = blockIdx.x*256 + warp*32 + lane;
  int tokbase = blockIdx.x*256 + warp*32;
  const float4* tok4 = (const float4*)tokens + (size_t)tokbase*128;
  float* xsw = xs[warp];
  const float4* G4 = (const float4*)g_G;

  ull acc[32];
  #pragma unroll
  for(int r=0;r<32;r++) acc[r]=0ull;
  ull sum2=0ull, ss2=0ull;

  for(int kc=0;kc<512;kc+=32){
    __syncthreads();
    { int r=tid>>3, kk=tid&7;
      ((float4*)Gc)[r*8+kk] = G4[r*128 + (kc>>2) + kk]; }
    #pragma unroll
    for(int j=0;j<8;j++){                       // FIXED: 8 iters -> 256 float4/warp
      int f=j*32+lane; int rowt=f>>3, c4=f&7;   // rowt 0..31, c4 0..7
      float4 v = tok4[rowt*128 + (kc>>2) + c4];
      *(float4*)&xsw[rowt*36 + c4*4] = v;
    }
    __syncthreads();
    #pragma unroll
    for(int k4=0;k4<8;k4++){
      ulonglong2 xv = *(const ulonglong2*)&xsw[lane*36 + k4*4];
      sum2 = fadd2(sum2, xv.x); sum2 = fadd2(sum2, xv.y);
      ss2  = ffma2(xv.x, xv.x, ss2); ss2 = ffma2(xv.y, xv.y, ss2);
      #pragma unroll
      for(int r=0;r<32;r++){
        ulonglong2 gv = *(const ulonglong2*)&Gc[r*32 + k4*4];
        acc[r] = ffma2(xv.x, gv.x, acc[r]);
        acc[r] = ffma2(xv.y, gv.y, acc[r]);
      }
    }
  }
  float2 sp = unpack2(sum2), qp2 = unpack2(ss2);
  float m = (sp.x+sp.y)*(1.f/512.f);
  float var = (qp2.x+qp2.y)*(1.f/512.f) - m*m;
  float rstd = rsqrtf(var + 1e-5f);
  int b = tok>>13, n = tok&8191;
  float* Sb = g_S + (size_t)b*32*8192 + n;
  #pragma unroll
  for(int r=0;r<32;r++){
    float2 a2 = unpack2(acc[r]);
    Sb[(size_t)r*8192] = rstd*((a2.x+a2.y) - m*As[r]);
  }
}

// ---------------- K4: per-(b,r) max & sumexp (512 blocks x 256 thr) ----------------
__device__ __forceinline__ void merge_ms(float& m, float& s, float m2, float s2){
  float M = fmaxf(m, m2);
  if(M == NEG_INF){ m = M; s = 0.f; return; }
  s = s*__expf(m-M) + s2*__expf(m2-M);
  m = M;
}
__global__ void k4(const void* mask){
  __shared__ float sm[8], ssu[8];
  int blk = blockIdx.x, b = blk>>5;
  int tid=threadIdx.x, warp=tid>>5, lane=tid&31;
  int mode = g_mask_mode;
  const float* row = g_S + (size_t)blk*8192;
  float lm = NEG_INF, ls = 0.f;
  for(int n=tid;n<8192;n+=256){
    if(!mask_at(mask, b*8192+n, mode)){
      float v = row[n];
      if(v > lm){ ls = ls*__expf(lm-v) + 1.f; lm = v; }
      else ls += __expf(v-lm);
    }
  }
  #pragma unroll
  for(int o=16;o;o>>=1){
    float m2 = __shfl_xor_sync(FULLMASK, lm, o);
    float s2 = __shfl_xor_sync(FULLMASK, ls, o);
    merge_ms(lm, ls, m2, s2);
  }
  if(lane==0){ sm[warp]=lm; ssu[warp]=ls; }
  __syncthreads();
  if(tid==0){
    float M=sm[0], S=ssu[0];
    #pragma unroll
    for(int w2=1;w2<8;w2++) merge_ms(M,S,sm[w2],ssu[w2]);
    g_M[blk]=M; g_Z[blk]=fmaxf(S,1e-30f);
  }
}

// ---------------- K5: alpha + partial sums (512 blocks x 256 thr) ----------------
__global__ void k5(const void* mask){
  __shared__ float Ms[8], iZ[8], red[8];
  int blk=blockIdx.x, bt=blk>>3, slice=blk&7;
  int b=bt>>2, t=bt&3;
  int tid=threadIdx.x, warp=tid>>5, lane=tid&31;
  int mode=g_mask_mode;
  if(tid<8){ Ms[tid]=g_M[b*32+t*8+tid]; iZ[tid]=1.f/g_Z[b*32+t*8+tid]; }
  __syncthreads();
  const float* Sb = g_S + (size_t)(b*32+t*8)*8192;
  float lsum=0.f;
  #pragma unroll
  for(int it=0;it<4;it++){
    int n = slice*1024 + it*256 + tid;
    float a = 0.f;
    if(!mask_at(mask, b*8192+n, mode)){
      #pragma unroll
      for(int h=0;h<8;h++)
        a += __expf(Sb[(size_t)h*8192+n]-Ms[h])*iZ[h];
      a *= 0.125f;
    }
    g_alpha[(size_t)bt*8192+n] = a;
    lsum += a;
  }
  lsum = wredsum(lsum);
  if(lane==0) red[warp]=lsum;
  __syncthreads();
  if(tid==0){
    float s=0.f;
    #pragma unroll
    for(int w2=0;w2<8;w2++) s+=red[w2];
    g_part[blk]=s;
  }
}

// ---------------- K6: prune + top-64 per (b,t) (64 blocks x 256 thr) ----------------
__global__ void k6(const void* mask){
  __shared__ ull cand[1024];
  __shared__ int cnt;
  __shared__ ull red8[8];
  __shared__ ull winner;
  __shared__ float sval[64];
  __shared__ int sidx[64];
  __shared__ float swsum;
  int bt=blockIdx.x, b=bt>>2;
  int tid=threadIdx.x, warp=tid>>5, lane=tid&31;
  int mode=g_mask_mode;
  if(tid==0){ cnt=0; swsum=0.f; }
  __syncthreads();
  float s1=0.f;
  #pragma unroll
  for(int i=0;i<8;i++) s1 += g_part[bt*8+i];
  float den = fmaxf(s1, 1e-8f);
  const float* al = g_alpha + (size_t)bt*8192;
  for(int n=tid;n<8192;n+=256){
    if(!mask_at(mask, b*8192+n, mode)){
      float av = al[n]/den;
      if(av >= 0.001f){
        int pos = atomicAdd(&cnt,1);
        if(pos<1024){
          ull key = (((ull)__float_as_uint(av))<<32) | (ull)(0x7FFFFFFFu - n);
          cand[pos]=key;
        }
      }
    }
  }
  __syncthreads();
  int C = min(cnt, 1024);
  if(C==0){
    ull lk=0;
    for(int n=tid;n<8192;n+=256){
      if(!mask_at(mask, b*8192+n, mode)){
        float av = al[n]/den;
        ull key = (((ull)__float_as_uint(av))<<32) | (ull)(0x7FFFFFFFu - n);
        if(key>lk) lk=key;
      }
    }
    #pragma unroll
    for(int o=16;o;o>>=1){ ull k2=__shfl_xor_sync(FULLMASK,lk,o); if(k2>lk)lk=k2; }
    if(lane==0) red8[warp]=lk;
    __syncthreads();
    if(tid==0){
      ull best=red8[0];
      #pragma unroll
      for(int w2=1;w2<8;w2++) if(red8[w2]>best) best=red8[w2];
      g_sel[bt*64+0] = 0x7FFFFFFF - (int)(best & 0xFFFFFFFFull);
      g_w[bt*64+0] = 1.f;
      g_cnt[bt]=1;
    }
    return;
  }
  int S = min(C, 64);
  for(int r=0;r<S;r++){
    ull lk=0;
    for(int i=tid;i<C;i+=256){ ull k=cand[i]; if(k>lk)lk=k; }
    #pragma unroll
    for(int o=16;o;o>>=1){ ull k2=__shfl_xor_sync(FULLMASK,lk,o); if(k2>lk)lk=k2; }
    if(lane==0) red8[warp]=lk;
    __syncthreads();
    if(tid==0){
      ull best=red8[0];
      #pragma unroll
      for(int w2=1;w2<8;w2++) if(red8[w2]>best) best=red8[w2];
      winner=best;
      float v = __uint_as_float((unsigned)(best>>32));
      sval[r]=v; sidx[r]=0x7FFFFFFF-(int)(best&0xFFFFFFFFull);
      swsum += v;
    }
    __syncthreads();
    ull wn = winner;
    for(int i=tid;i<C;i+=256) if(cand[i]==wn) cand[i]=0ull;
    __syncthreads();
  }
  float iw = 1.f/fmaxf(swsum, 1e-8f);
  if(tid<S){
    g_sel[bt*64+tid]=sidx[tid];
    g_w[bt*64+tid]=sval[tid]*iw;
  }
  if(tid==0) g_cnt[bt]=S;
}

// ---------------- K7: gather + pool + wv matvec (64 blocks x 256 thr) ----------------
__global__ void k7(const float* tokens, const float* W, const float* bias,
                   const float* preg, const float* preb, float* out){
  __shared__ float zsh[8][512];
  __shared__ float z[512];
  int bt=blockIdx.x, b=bt>>2;
  int tid=threadIdx.x, warp=tid>>5, lane=tid&31;
  int S = g_cnt[bt];
  float zacc[16];
  #pragma unroll
  for(int i=0;i<16;i++) zacc[i]=0.f;
  for(int k=warp;k<S;k+=8){
    int idx = g_sel[bt*64+k];
    float wk = g_w[bt*64+k];
    const float4* row = (const float4*)(tokens + ((size_t)b*8192+idx)*512);
    float4 x[4]; float s=0.f, ss=0.f;
    #pragma unroll
    for(int j=0;j<4;j++){
      x[j]=row[lane+32*j];
      s += x[j].x+x[j].y+x[j].z+x[j].w;
      ss += x[j].x*x[j].x+x[j].y*x[j].y+x[j].z*x[j].z+x[j].w*x[j].w;
    }
    s=wredsum(s); ss=wredsum(ss);
    float m=s*(1.f/512.f);
    float rstd=rsqrtf(ss*(1.f/512.f)-m*m+1e-5f);
    #pragma unroll
    for(int j=0;j<4;j++){
      int d0=(lane+32*j)*4;
      float v[4]={x[j].x,x[j].y,x[j].z,x[j].w};
      #pragma unroll
      for(int c=0;c<4;c++){
        int d=d0+c;
        zacc[j*4+c] += wk*((v[c]-m)*rstd*preg[d]+preb[d]);
      }
    }
  }
  #pragma unroll
  for(int j=0;j<4;j++)
    #pragma unroll
    for(int c=0;c<4;c++)
      zsh[warp][(lane+32*j)*4+c]=zacc[j*4+c];
  __syncthreads();
  #pragma unroll
  for(int rep=0;rep<2;rep++){
    int d = tid+rep*256;
    float a=0.f;
    #pragma unroll
    for(int w2=0;w2<8;w2++) a+=zsh[w2][d];
    z[d]=a;
  }
  __syncthreads();
  const float4* z4=(const float4*)z;
  for(int o=warp;o<512;o+=8){
    const float4* wr=(const float4*)(W+(size_t)(1024+o)*512);
    float a=0.f;
    #pragma unroll
    for(int j=0;j<4;j++){
      float4 A=z4[lane+32*j], B=wr[lane+32*j];
      a += A.x*B.x+A.y*B.y+A.z*B.z+A.w*B.w;
    }
    a=wredsum(a);
    if(lane==0) out[(size_t)bt*512+o]=a+bias[1024+o];
  }
}

// ---------------- launch ----------------
extern "C" void kernel_launch(void* const* d_in, const int* in_sizes, int n_in,
                              void* d_out, int out_size) {
  const float* tokens = (const float*)d_in[0];
  const void*  mask   = d_in[1];
  const float* q      = (const float*)d_in[2];
  const float* W      = (const float*)d_in[3];
  const float* bias   = (const float*)d_in[4];
  const float* preg   = (const float*)d_in[5];
  const float* preb   = (const float*)d_in[6];
  const float* qg     = (const float*)d_in[7];
  const float* qb     = (const float*)d_in[8];
  const float* logtau = (const float*)d_in[9];
  float* out = (float*)d_out;

  kdetect<<<1,256>>>((const unsigned char*)mask);
  k0<<<1,128>>>(q, qg, qb, logtau);
  k1<<<64,256>>>(W, bias);
  k2<<<32,256>>>(W, preg);
  k3<<<512,256>>>(tokens);
  k4<<<512,256>>>(mask);
  k5<<<512,256>>>(mask);
  k6<<<64,256>>>(mask);
  k7<<<64,256>>>(tokens, W, bias, preg, preb, out);
}

// round 10
// speedup vs baseline: 1.2609x; 1.2609x over previous
#include <cuda_runtime.h>
#include <cuda_bf16.h>
#include <math_constants.h>

typedef unsigned long long ull;
#define FULLMASK 0xffffffffu
#define NEG_INF (-CUDART_INF_F)

// ---------------- scratch ----------------
__device__ float g_S[16*32*8192];     // scores [b][r][n]
__device__ float g_alpha[64*8192];    // [bt][n]
__device__ float g_part[512];         // partial alpha sums [bt*8+slice]
__device__ float g_Zp[4096*32];       // per-tile Z partials [tile][r]
__device__ float g_G[32*512];
__device__ float g_A[32];
__device__ float g_qp[4*512];
__device__ int   g_sel[64*64];
__device__ float g_w[64*64];
__device__ int   g_cnt[64];
__device__ int   g_mask_mode;
__device__ int   g_tile;              // work-stealing counter for k3

// ---------------- helpers ----------------
__device__ __forceinline__ ull ffma2(ull a, ull b, ull c){
  ull d; asm("fma.rn.f32x2 %0, %1, %2, %3;" : "=l"(d) : "l"(a), "l"(b), "l"(c)); return d;
}
__device__ __forceinline__ ull fadd2(ull a, ull b){
  ull d; asm("add.rn.f32x2 %0, %1, %2;" : "=l"(d) : "l"(a), "l"(b)); return d;
}
__device__ __forceinline__ float2 unpack2(ull v){
  float2 r; asm("mov.b64 {%0, %1}, %2;" : "=f"(r.x), "=f"(r.y) : "l"(v)); return r;
}
__device__ __forceinline__ float wredsum(float v){
  #pragma unroll
  for(int o=16;o;o>>=1) v += __shfl_xor_sync(FULLMASK, v, o);
  return v;
}
__device__ __forceinline__ bool mask_at(const void* m, int idx, int mode){
  if(mode==0) return ((const unsigned char*)m)[idx]!=0;
  if(mode==1) return ((const int*)m)[idx]!=0;
  if(mode==2) return ((const float*)m)[idx]!=0.f;
  return (((const unsigned short*)m)[idx]&0x7fff)!=0;
}

// ---------------- K1: fused mask-detect + LN(q)/tau + qp ----------------
// blocks 0..63: qp slices (each block redundantly computes LN(q) in smem)
// block 64: mask dtype detection
__global__ void k1f(const float* q, const float* qg, const float* qb,
                    const float* logtau, const float* W, const float* bias,
                    const unsigned char* mraw){
  __shared__ float queryS[4*512];
  __shared__ int f2[2];
  int tid=threadIdx.x, warp=tid>>5, lane=tid&31;

  if(blockIdx.x==64){
    if(tid<2) f2[tid]=0;
    __syncthreads();
    int gt1=0, nz1=0;
    for(int i=tid;i<65536;i+=256){
      unsigned char c=mraw[i];
      if(c>1) gt1=1;
      if(c && ((i&3)==1)) nz1=1;
    }
    if(gt1) atomicOr(&f2[0],1);
    if(nz1) atomicOr(&f2[1],1);
    __syncthreads();
    if(tid==0){
      int mode;
      if(!f2[0]) mode = f2[1] ? 0 : 1;   // u8 bool vs int32
      else       mode = f2[1] ? 3 : 2;   // bf16 vs f32
      g_mask_mode = mode;
    }
    return;
  }

  if(warp<4){  // LN for t=warp
    float tau = fminf(fmaxf(__expf(logtau[0]), 0.1f), 10.f);
    float inv_tau = 1.f/tau;
    const float4* qr = (const float4*)(q + warp*512);
    float4 x[4]; float s=0.f, ss=0.f;
    #pragma unroll
    for(int j=0;j<4;j++){
      x[j]=qr[lane+32*j];
      s += x[j].x+x[j].y+x[j].z+x[j].w;
      ss += x[j].x*x[j].x + x[j].y*x[j].y + x[j].z*x[j].z + x[j].w*x[j].w;
    }
    s = wredsum(s); ss = wredsum(ss);
    float m = s*(1.f/512.f);
    float rstd = rsqrtf(ss*(1.f/512.f) - m*m + 1e-5f);
    #pragma unroll
    for(int j=0;j<4;j++){
      int d0=(lane+32*j)*4;
      float v[4]={x[j].x,x[j].y,x[j].z,x[j].w};
      #pragma unroll
      for(int c=0;c<4;c++){
        int d=d0+c;
        queryS[warp*512+d] = ((v[c]-m)*rstd*qg[d] + qb[d]) * inv_tau;
      }
    }
  }
  __syncthreads();

  int w = blockIdx.x*8 + warp;
  #pragma unroll
  for(int qq=0;qq<4;qq++){
    int p = w*4+qq;
    int t = p>>9, o = p&511;
    const float4* qr = (const float4*)(queryS + t*512);
    const float4* wr = (const float4*)(W + (size_t)o*512);
    float a=0.f;
    #pragma unroll
    for(int j=0;j<4;j++){
      float4 A=qr[lane+32*j], B=wr[lane+32*j];
      a += A.x*B.x + A.y*B.y + A.z*B.z + A.w*B.w;
    }
    a = wredsum(a);
    if(lane==0) g_qp[t*512+o] = a + bias[o];
  }
}

// ---------------- K2: G[r][d], A[r] (8 blocks per h, 512 thr, coalesced) ----------------
__global__ void k2(const float* W, const float* preg){
  __shared__ float qv[4][64];
  __shared__ float redA[4][16];
  int h=blockIdx.x, tid=threadIdx.x, warp=tid>>5, lane=tid&31;
  if(h==0 && tid==0) g_tile = 0;        // reset k3 work-stealing counter
  if(tid<256){ int t=tid>>6, j=tid&63; qv[t][j]=g_qp[t*512+h*64+j]; }
  __syncthreads();
  int d = tid;  // 512 threads == 512 d
  const float* base = W + (size_t)(512 + h*64)*512 + d;
  float acc[4]={0.f,0.f,0.f,0.f};
  #pragma unroll 4
  for(int j=0;j<64;j++){
    float wv = base[(size_t)j*512];
    acc[0]+=qv[0][j]*wv; acc[1]+=qv[1][j]*wv;
    acc[2]+=qv[2][j]*wv; acc[3]+=qv[3][j]*wv;
  }
  float pg = preg[d];
  #pragma unroll
  for(int t=0;t<4;t++){
    float gval = pg*acc[t]*0.125f;   // fold 1/sqrt(64)
    g_G[(t*8+h)*512+d]=gval;
    float v = wredsum(gval);
    if(lane==0) redA[t][warp]=v;
  }
  __syncthreads();
  if(tid<4){
    float a=0.f;
    #pragma unroll
    for(int i=0;i<16;i++) a+=redA[tid][i];
    g_A[tid*8+h]=a;
  }
}

// ---------------- K3: streaming scores + Z partials (work-stealing) ----------------
// grid 296 x 256 thr, 2 blocks/SM. dyn smem: G[16384] + xs[8*1152] + As[32]
__global__ void __launch_bounds__(256,2) k3(const float* tokens, const void* mask){
  extern __shared__ float sh[];
  float* Gs  = sh;               // 16384 floats
  float* xsA = sh + 16384;       // 8*1152
  float* As  = sh + 16384 + 9216;// 32
  int tid=threadIdx.x, warp=tid>>5, lane=tid&31;
  for(int i=tid;i<4096;i+=256) ((float4*)Gs)[i] = ((const float4*)g_G)[i];
  if(tid<32) As[tid]=g_A[tid];
  __syncthreads();

  int mode = g_mask_mode;
  float* xsw = xsA + warp*1152;
  const float4* tok4 = (const float4*)tokens;

  for(;;){
    int tile;
    if(lane==0) tile = atomicAdd(&g_tile, 1);
    tile = __shfl_sync(FULLMASK, tile, 0);
    if(tile >= 4096) break;

    ull acc[32];
    #pragma unroll
    for(int r=0;r<32;r++) acc[r]=0ull;
    ull sum2=0ull, ss2=0ull;
    size_t rowbase = (size_t)tile*32*128;

    for(int kc=0;kc<512;kc+=32){
      __syncwarp();
      #pragma unroll
      for(int j=0;j<8;j++){
        int f=j*32+lane; int rowt=f>>3, c4=f&7;
        float4 v = tok4[rowbase + (size_t)rowt*128 + (kc>>2) + c4];
        *(float4*)&xsw[rowt*36 + c4*4] = v;
      }
      __syncwarp();
      #pragma unroll
      for(int k4=0;k4<8;k4++){
        ulonglong2 xv = *(const ulonglong2*)&xsw[lane*36 + k4*4];
        sum2 = fadd2(sum2, xv.x); sum2 = fadd2(sum2, xv.y);
        ss2  = ffma2(xv.x, xv.x, ss2); ss2 = ffma2(xv.y, xv.y, ss2);
        #pragma unroll
        for(int r=0;r<32;r++){
          const ulonglong2 gv = *(const ulonglong2*)&Gs[r*512 + kc + k4*4];
          acc[r] = ffma2(xv.x, gv.x, acc[r]);
          acc[r] = ffma2(xv.y, gv.y, acc[r]);
        }
      }
    }
    float2 sp = unpack2(sum2), qp2 = unpack2(ss2);
    float m = (sp.x+sp.y)*(1.f/512.f);
    float var = (qp2.x+qp2.y)*(1.f/512.f) - m*m;
    float rstd = rsqrtf(var + 1e-5f);
    int tok = tile*32 + lane;
    int b = tok>>13, n = tok&8191;
    bool msk = mask_at(mask, tok, mode);
    float* Sb = g_S + (size_t)b*32*8192 + n;
    float myZ = 0.f;
    #pragma unroll
    for(int r=0;r<32;r++){
      float2 a2 = unpack2(acc[r]);
      float sc = rstd*((a2.x+a2.y) - m*As[r]);
      Sb[(size_t)r*8192] = sc;
      float e = msk ? 0.f : __expf(sc);
      #pragma unroll
      for(int o=16;o;o>>=1) e += __shfl_xor_sync(FULLMASK, e, o);
      if(r==lane) myZ = e;
    }
    g_Zp[tile*32+lane] = myZ;
  }
}

// ---------------- K5: Z reduce + alpha + partial sums (512 blocks x 256) ----------------
__global__ void k5(const void* mask){
  __shared__ float zp[8][16];
  __shared__ float iZ[8], red[8];
  int blk=blockIdx.x, bt=blk>>3, slice=blk&7;
  int b=bt>>2, t=bt&3;
  int tid=threadIdx.x, warp=tid>>5, lane=tid&31;
  int mode=g_mask_mode;
  if(tid<128){
    int h=tid>>4, i0=tid&15;
    float s=0.f;
    for(int p=i0;p<256;p+=16) s += g_Zp[(b*256+p)*32 + t*8+h];
    zp[h][i0]=s;
  }
  __syncthreads();
  if(tid<8){
    float s=0.f;
    #pragma unroll
    for(int i=0;i<16;i++) s+=zp[tid][i];
    iZ[tid]=1.f/fmaxf(s,1e-30f);
  }
  __syncthreads();
  const float* Sb = g_S + (size_t)(b*32+t*8)*8192;
  float lsum=0.f;
  #pragma unroll
  for(int it=0;it<4;it++){
    int n = slice*1024 + it*256 + tid;
    float a = 0.f;
    if(!mask_at(mask, b*8192+n, mode)){
      #pragma unroll
      for(int h=0;h<8;h++)
        a += __expf(Sb[(size_t)h*8192+n])*iZ[h];
      a *= 0.125f;
    }
    g_alpha[(size_t)bt*8192+n] = a;
    lsum += a;
  }
  lsum = wredsum(lsum);
  if(lane==0) red[warp]=lsum;
  __syncthreads();
  if(tid==0){
    float s=0.f;
    #pragma unroll
    for(int w2=0;w2<8;w2++) s+=red[w2];
    g_part[blk]=s;
  }
}

// ---------------- K6: prune + top-64 via rank counting (64 blocks x 256) ----------------
__global__ void k6(const void* mask){
  __shared__ ull cand[1024];
  __shared__ int cnt;
  __shared__ ull red8[8];
  __shared__ float sval[64];
  __shared__ int sidx[64];
  __shared__ float swsum;
  int bt=blockIdx.x, b=bt>>2;
  int tid=threadIdx.x, warp=tid>>5, lane=tid&31;
  int mode=g_mask_mode;
  if(tid==0) cnt=0;
  __syncthreads();
  float den=0.f;
  #pragma unroll
  for(int i=0;i<8;i++) den += g_part[bt*8+i];
  float inv_den = 1.f/fmaxf(den, 1e-8f);
  const float* al = g_alpha + (size_t)bt*8192;
  for(int n=tid;n<8192;n+=256){
    if(!mask_at(mask, b*8192+n, mode)){
      float av = al[n]*inv_den;
      if(av >= 0.001f){
        int pos = atomicAdd(&cnt,1);
        if(pos<1024){
          ull key = (((ull)__float_as_uint(av))<<32) | (ull)(0x7FFFFFFFu - n);
          cand[pos]=key;
        }
      }
    }
  }
  __syncthreads();
  int C = min(cnt, 1024);
  if(C==0){
    // fallback: argmax of alpha over unmasked (tie lowest index)
    ull lk=0;
    for(int n=tid;n<8192;n+=256){
      if(!mask_at(mask, b*8192+n, mode)){
        ull key = (((ull)__float_as_uint(al[n]))<<32) | (ull)(0x7FFFFFFFu - n);
        if(key>lk) lk=key;
      }
    }
    #pragma unroll
    for(int o=16;o;o>>=1){ ull k2v=__shfl_xor_sync(FULLMASK,lk,o); if(k2v>lk)lk=k2v; }
    if(lane==0) red8[warp]=lk;
    __syncthreads();
    if(tid==0){
      ull best=red8[0];
      #pragma unroll
      for(int w2=1;w2<8;w2++) if(red8[w2]>best) best=red8[w2];
      int idx = best ? (0x7FFFFFFF - (int)(best & 0xFFFFFFFFull)) : 0;
      g_sel[bt*64+0]=idx; g_w[bt*64+0]=1.f; g_cnt[bt]=1;
    }
    return;
  }
  // rank counting: count of strictly-greater keys = unique slot
  {
    ull my[4]; int mi[4]; int nm=0;
    for(int i=tid;i<C;i+=256){ my[nm]=cand[i]; mi[nm]=i; nm++; }
    int cgt[4]={0,0,0,0};
    for(int j=0;j<C;j++){
      ull kj = cand[j];
      #pragma unroll
      for(int u=0;u<4;u++) if(u<nm && kj>my[u]) cgt[u]++;
    }
    #pragma unroll
    for(int u=0;u<4;u++){
      if(u<nm && cgt[u]<64){
        sval[cgt[u]] = __uint_as_float((unsigned)(my[u]>>32));
        sidx[cgt[u]] = 0x7FFFFFFF - (int)(my[u]&0xFFFFFFFFull);
      }
    }
  }
  __syncthreads();
  int S = min(C,64);
  if(tid<32){
    float s=0.f;
    for(int i=lane;i<S;i+=32) s+=sval[i];
    s=wredsum(s);
    if(lane==0) swsum=s;
  }
  __syncthreads();
  float iw = 1.f/fmaxf(swsum, 1e-8f);
  if(tid<S){
    g_sel[bt*64+tid]=sidx[tid];
    g_w[bt*64+tid]=sval[tid]*iw;
  }
  if(tid==0) g_cnt[bt]=S;
}

// ---------------- K7: gather + pool + wv matvec (64 blocks x 256) ----------------
__global__ void k7(const float* tokens, const float* W, const float* bias,
                   const float* preg, const float* preb, float* out){
  __shared__ float zsh[8][512];
  __shared__ float z[512];
  int bt=blockIdx.x, b=bt>>2;
  int tid=threadIdx.x, warp=tid>>5, lane=tid&31;
  int S = g_cnt[bt];
  float zacc[16];
  #pragma unroll
  for(int i=0;i<16;i++) zacc[i]=0.f;
  for(int k=warp;k<S;k+=8){
    int idx = g_sel[bt*64+k];
    float wk = g_w[bt*64+k];
    const float4* row = (const float4*)(tokens + ((size_t)b*8192+idx)*512);
    float4 x[4]; float s=0.f, ss=0.f;
    #pragma unroll
    for(int j=0;j<4;j++){
      x[j]=row[lane+32*j];
      s += x[j].x+x[j].y+x[j].z+x[j].w;
      ss += x[j].x*x[j].x+x[j].y*x[j].y+x[j].z*x[j].z+x[j].w*x[j].w;
    }
    s=wredsum(s); ss=wredsum(ss);
    float m=s*(1.f/512.f);
    float rstd=rsqrtf(ss*(1.f/512.f)-m*m+1e-5f);
    #pragma unroll
    for(int j=0;j<4;j++){
      int d0=(lane+32*j)*4;
      float v[4]={x[j].x,x[j].y,x[j].z,x[j].w};
      #pragma unroll
      for(int c=0;c<4;c++){
        int d=d0+c;
        zacc[j*4+c] += wk*((v[c]-m)*rstd*preg[d]+preb[d]);
      }
    }
  }
  #pragma unroll
  for(int j=0;j<4;j++)
    #pragma unroll
    for(int c=0;c<4;c++)
      zsh[warp][(lane+32*j)*4+c]=zacc[j*4+c];
  __syncthreads();
  #pragma unroll
  for(int rep=0;rep<2;rep++){
    int d = tid+rep*256;
    float a=0.f;
    #pragma unroll
    for(int w2=0;w2<8;w2++) a+=zsh[w2][d];
    z[d]=a;
  }
  __syncthreads();
  const float4* z4=(const float4*)z;
  for(int o=warp;o<512;o+=8){
    const float4* wr=(const float4*)(W+(size_t)(1024+o)*512);
    float a=0.f;
    #pragma unroll
    for(int j=0;j<4;j++){
      float4 A=z4[lane+32*j], B=wr[lane+32*j];
      a += A.x*B.x+A.y*B.y+A.z*B.z+A.w*B.w;
    }
    a=wredsum(a);
    if(lane==0) out[(size_t)bt*512+o]=a+bias[1024+o];
  }
}

// ---------------- launch ----------------
extern "C" void kernel_launch(void* const* d_in, const int* in_sizes, int n_in,
                              void* d_out, int out_size) {
  const float* tokens = (const float*)d_in[0];
  const void*  mask   = d_in[1];
  const float* q      = (const float*)d_in[2];
  const float* W      = (const float*)d_in[3];
  const float* bias   = (const float*)d_in[4];
  const float* preg   = (const float*)d_in[5];
  const float* preb   = (const float*)d_in[6];
  const float* qg     = (const float*)d_in[7];
  const float* qb     = (const float*)d_in[8];
  const float* logtau = (const float*)d_in[9];
  float* out = (float*)d_out;

  const int K3_SMEM = (16384 + 8*1152 + 32) * 4;   // 102528 B
  static int attr_done = 0;
  if(!attr_done){
    cudaFuncSetAttribute(k3, cudaFuncAttributeMaxDynamicSharedMemorySize, K3_SMEM);
    attr_done = 1;
  }

  k1f<<<65,256>>>(q, qg, qb, logtau, W, bias, (const unsigned char*)mask);
  k2<<<8,512>>>(W, preg);
  k3<<<296,256,K3_SMEM>>>(tokens, mask);
  k5<<<512,256>>>(mask);
  k6<<<64,256>>>(mask);
  k7<<<64,256>>>(tokens, W, bias, preg, preb, out);
}

// round 11
// speedup vs baseline: 1.3376x; 1.0609x over previous
#include <cuda_runtime.h>
#include <cuda_bf16.h>
#include <math_constants.h>

typedef unsigned long long ull;
#define FULLMASK 0xffffffffu
#define NEG_INF (-CUDART_INF_F)

// ---------------- scratch ----------------
__device__ float g_S[16*32*8192];     // scores [b][r][n]
__device__ float g_alpha[64*8192];    // [bt][n]
__device__ float g_part[1024];        // partial alpha sums [bt*16+slice]
__device__ float g_Zp[4096*32];       // per-tile Z partials [tile][r]
__device__ float g_G[32*512];
__device__ float g_A[32];
__device__ float g_qp[4*512];
__device__ int   g_sel[64*64];
__device__ float g_w[64*64];
__device__ int   g_cnt[64];
__device__ int   g_mask_mode;
__device__ int   g_tile;              // work-stealing counter for k3

// ---------------- helpers ----------------
__device__ __forceinline__ ull ffma2(ull a, ull b, ull c){
  ull d; asm("fma.rn.f32x2 %0, %1, %2, %3;" : "=l"(d) : "l"(a), "l"(b), "l"(c)); return d;
}
__device__ __forceinline__ ull fadd2(ull a, ull b){
  ull d; asm("add.rn.f32x2 %0, %1, %2;" : "=l"(d) : "l"(a), "l"(b)); return d;
}
__device__ __forceinline__ float2 unpack2(ull v){
  float2 r; asm("mov.b64 {%0, %1}, %2;" : "=f"(r.x), "=f"(r.y) : "l"(v)); return r;
}
__device__ __forceinline__ float wredsum(float v){
  #pragma unroll
  for(int o=16;o;o>>=1) v += __shfl_xor_sync(FULLMASK, v, o);
  return v;
}
__device__ __forceinline__ bool mask_at(const void* m, int idx, int mode){
  if(mode==0) return ((const unsigned char*)m)[idx]!=0;
  if(mode==1) return ((const int*)m)[idx]!=0;
  if(mode==2) return ((const float*)m)[idx]!=0.f;
  return (((const unsigned short*)m)[idx]&0x7fff)!=0;
}
__device__ __forceinline__ void barp(int pair){
  asm volatile("bar.sync %0, %1;" :: "r"(pair+1), "r"(64) : "memory");
}

// ---------------- K1: fused mask-detect + LN(q)/tau + qp ----------------
__global__ void k1f(const float* q, const float* qg, const float* qb,
                    const float* logtau, const float* W, const float* bias,
                    const unsigned char* mraw){
  __shared__ float queryS[4*512];
  __shared__ int f2[2];
  int tid=threadIdx.x, warp=tid>>5, lane=tid&31;

  if(blockIdx.x==64){
    if(tid<2) f2[tid]=0;
    __syncthreads();
    int gt1=0, nz1=0;
    for(int i=tid;i<65536;i+=256){
      unsigned char c=mraw[i];
      if(c>1) gt1=1;
      if(c && ((i&3)==1)) nz1=1;
    }
    if(gt1) atomicOr(&f2[0],1);
    if(nz1) atomicOr(&f2[1],1);
    __syncthreads();
    if(tid==0){
      int mode;
      if(!f2[0]) mode = f2[1] ? 0 : 1;   // u8 bool vs int32
      else       mode = f2[1] ? 3 : 2;   // bf16 vs f32
      g_mask_mode = mode;
    }
    return;
  }

  if(warp<4){  // LN for t=warp
    float tau = fminf(fmaxf(__expf(logtau[0]), 0.1f), 10.f);
    float inv_tau = 1.f/tau;
    const float4* qr = (const float4*)(q + warp*512);
    float4 x[4]; float s=0.f, ss=0.f;
    #pragma unroll
    for(int j=0;j<4;j++){
      x[j]=qr[lane+32*j];
      s += x[j].x+x[j].y+x[j].z+x[j].w;
      ss += x[j].x*x[j].x + x[j].y*x[j].y + x[j].z*x[j].z + x[j].w*x[j].w;
    }
    s = wredsum(s); ss = wredsum(ss);
    float m = s*(1.f/512.f);
    float rstd = rsqrtf(ss*(1.f/512.f) - m*m + 1e-5f);
    #pragma unroll
    for(int j=0;j<4;j++){
      int d0=(lane+32*j)*4;
      float v[4]={x[j].x,x[j].y,x[j].z,x[j].w};
      #pragma unroll
      for(int c=0;c<4;c++){
        int d=d0+c;
        queryS[warp*512+d] = ((v[c]-m)*rstd*qg[d] + qb[d]) * inv_tau;
      }
    }
  }
  __syncthreads();

  int w = blockIdx.x*8 + warp;
  #pragma unroll
  for(int qq=0;qq<4;qq++){
    int p = w*4+qq;
    int t = p>>9, o = p&511;
    const float4* qr = (const float4*)(queryS + t*512);
    const float4* wr = (const float4*)(W + (size_t)o*512);
    float a=0.f;
    #pragma unroll
    for(int j=0;j<4;j++){
      float4 A=qr[lane+32*j], B=wr[lane+32*j];
      a += A.x*B.x + A.y*B.y + A.z*B.z + A.w*B.w;
    }
    a = wredsum(a);
    if(lane==0) g_qp[t*512+o] = a + bias[o];
  }
}

// ---------------- K2: G[r][d], A[r] (8 blocks, 512 thr) ----------------
__global__ void k2(const float* W, const float* preg){
  __shared__ float qv[4][64];
  __shared__ float redA[4][16];
  int h=blockIdx.x, tid=threadIdx.x, warp=tid>>5, lane=tid&31;
  if(h==0 && tid==0) g_tile = 0;
  if(tid<256){ int t=tid>>6, j=tid&63; qv[t][j]=g_qp[t*512+h*64+j]; }
  __syncthreads();
  int d = tid;
  const float* base = W + (size_t)(512 + h*64)*512 + d;
  float acc[4]={0.f,0.f,0.f,0.f};
  #pragma unroll 8
  for(int j=0;j<64;j++){
    float wv = base[(size_t)j*512];
    acc[0]+=qv[0][j]*wv; acc[1]+=qv[1][j]*wv;
    acc[2]+=qv[2][j]*wv; acc[3]+=qv[3][j]*wv;
  }
  float pg = preg[d];
  #pragma unroll
  for(int t=0;t<4;t++){
    float gval = pg*acc[t]*0.125f;
    g_G[(t*8+h)*512+d]=gval;
    float v = wredsum(gval);
    if(lane==0) redA[t][warp]=v;
  }
  __syncthreads();
  if(tid<4){
    float a=0.f;
    #pragma unroll
    for(int i=0;i<16;i++) a+=redA[tid][i];
    g_A[tid*8+h]=a;
  }
}

// ---------------- K3: streaming scores + Z (warp-pair r-split, double buffer) ----
// grid 296 x 256 thr, 2 blocks/SM. pair = 2 warps share a 32-token tile:
// warp A computes r 0..15, warp B r 16..31. acc[16] => 32 regs, no spills.
__global__ void __launch_bounds__(256,2) k3(const float* tokens, const void* mask){
  extern __shared__ float sh[];
  float* Gs  = sh;                        // 16384 floats
  float* xsA = sh + 16384;                // 4 pairs * 2 bufs * 1152
  float* As  = sh + 16384 + 9216;         // 32
  int*  tileS= (int*)(As + 32);           // 4
  int tid=threadIdx.x, warp=tid>>5, lane=tid&31;
  int pair=warp>>1, t64=tid&63;
  int r0 = (warp&1)*16;
  for(int i=tid;i<4096;i+=256) ((float4*)Gs)[i] = ((const float4*)g_G)[i];
  if(tid<32) As[tid]=g_A[tid];
  __syncthreads();

  int mode = g_mask_mode;
  float* xb0 = xsA + pair*2304;
  float* xb1 = xb0 + 1152;
  const float4* tok4 = (const float4*)tokens;

  for(;;){
    barp(pair);
    if(t64==0) tileS[pair] = atomicAdd(&g_tile, 1);
    barp(pair);
    int tile = tileS[pair];
    if(tile >= 4096) break;

    ull acc[16];
    #pragma unroll
    for(int i=0;i<16;i++) acc[i]=0ull;
    ull sum2=0ull, ss2=0ull;
    size_t rowbase = (size_t)tile*32*128;

    // stage chunk 0 into xb0
    #pragma unroll
    for(int j=0;j<4;j++){
      int f=j*64+t64; int rowt=f>>3, c4=f&7;
      *(float4*)&xb0[rowt*36 + c4*4] = tok4[rowbase + (size_t)rowt*128 + c4];
    }
    #pragma unroll 1
    for(int c=0;c<16;c++){
      barp(pair);
      float* xb = (c&1) ? xb1 : xb0;
      if(c<15){           // stage chunk c+1 into other buffer
        float* xn = (c&1) ? xb0 : xb1;
        int kq = (c+1)*8;
        #pragma unroll
        for(int j=0;j<4;j++){
          int f=j*64+t64; int rowt=f>>3, c4=f&7;
          *(float4*)&xn[rowt*36 + c4*4] = tok4[rowbase + (size_t)rowt*128 + kq + c4];
        }
      }
      int kc = c*32;
      #pragma unroll
      for(int k4=0;k4<8;k4++){
        ulonglong2 xv = *(const ulonglong2*)&xb[lane*36 + k4*4];
        sum2 = fadd2(sum2, xv.x); sum2 = fadd2(sum2, xv.y);
        ss2  = ffma2(xv.x, xv.x, ss2); ss2 = ffma2(xv.y, xv.y, ss2);
        #pragma unroll
        for(int i=0;i<16;i++){
          const ulonglong2 gv = *(const ulonglong2*)&Gs[(r0+i)*512 + kc + k4*4];
          acc[i] = ffma2(xv.x, gv.x, acc[i]);
          acc[i] = ffma2(xv.y, gv.y, acc[i]);
        }
      }
    }
    float2 sp = unpack2(sum2), qp2 = unpack2(ss2);
    float m = (sp.x+sp.y)*(1.f/512.f);
    float var = (qp2.x+qp2.y)*(1.f/512.f) - m*m;
    float rstd = rsqrtf(var + 1e-5f);
    int tok = tile*32 + lane;
    int b = tok>>13, n = tok&8191;
    bool msk = mask_at(mask, tok, mode);
    float* Sb = g_S + (size_t)b*32*8192 + n;
    float myZ = 0.f;
    #pragma unroll
    for(int i=0;i<16;i++){
      float2 a2 = unpack2(acc[i]);
      float sc = rstd*((a2.x+a2.y) - m*As[r0+i]);
      Sb[(size_t)(r0+i)*8192] = sc;
      float e = msk ? 0.f : __expf(sc);
      #pragma unroll
      for(int o=16;o;o>>=1) e += __shfl_xor_sync(FULLMASK, e, o);
      if(i==lane) myZ = e;
    }
    if(lane<16) g_Zp[tile*32 + r0 + lane] = myZ;
  }
}

// ---------------- K5: Z reduce + alpha + partials (1024 blocks x 256) ----------------
__global__ void k5(const void* mask){
  __shared__ float zp[8][16];
  __shared__ float iZ[8], red[8];
  int blk=blockIdx.x, bt=blk>>4, slice=blk&15;
  int b=bt>>2, t=bt&3;
  int tid=threadIdx.x, warp=tid>>5, lane=tid&31;
  int mode=g_mask_mode;
  if(tid<128){
    int h=tid>>4, i0=tid&15;
    float s=0.f;
    for(int p=i0;p<256;p+=16) s += g_Zp[(b*256+p)*32 + t*8+h];
    zp[h][i0]=s;
  }
  __syncthreads();
  if(tid<8){
    float s=0.f;
    #pragma unroll
    for(int i=0;i<16;i++) s+=zp[tid][i];
    iZ[tid]=1.f/fmaxf(s,1e-30f);
  }
  __syncthreads();
  const float* Sb = g_S + (size_t)(b*32+t*8)*8192;
  float lsum=0.f;
  #pragma unroll
  for(int it=0;it<2;it++){
    int n = slice*512 + it*256 + tid;
    float a = 0.f;
    if(!mask_at(mask, b*8192+n, mode)){
      #pragma unroll
      for(int h=0;h<8;h++)
        a += __expf(Sb[(size_t)h*8192+n])*iZ[h];
      a *= 0.125f;
    }
    g_alpha[(size_t)bt*8192+n] = a;
    lsum += a;
  }
  lsum = wredsum(lsum);
  if(lane==0) red[warp]=lsum;
  __syncthreads();
  if(tid==0){
    float s=0.f;
    #pragma unroll
    for(int w2=0;w2<8;w2++) s+=red[w2];
    g_part[blk]=s;
  }
}

// ---------------- K6: prune + top-64 via rank counting (64 blocks x 256) ----------------
__global__ void k6(const void* mask){
  __shared__ ull cand[1024];
  __shared__ int cnt;
  __shared__ ull red8[8];
  __shared__ float sval[64];
  __shared__ int sidx[64];
  __shared__ float swsum;
  int bt=blockIdx.x, b=bt>>2;
  int tid=threadIdx.x, warp=tid>>5, lane=tid&31;
  int mode=g_mask_mode;
  if(tid==0) cnt=0;
  __syncthreads();
  float den=0.f;
  #pragma unroll
  for(int i=0;i<16;i++) den += g_part[bt*16+i];
  float inv_den = 1.f/fmaxf(den, 1e-8f);
  const float* al = g_alpha + (size_t)bt*8192;
  for(int n=tid;n<8192;n+=256){
    if(!mask_at(mask, b*8192+n, mode)){
      float av = al[n]*inv_den;
      if(av >= 0.001f){
        int pos = atomicAdd(&cnt,1);
        if(pos<1024){
          ull key = (((ull)__float_as_uint(av))<<32) | (ull)(0x7FFFFFFFu - n);
          cand[pos]=key;
        }
      }
    }
  }
  __syncthreads();
  int C = min(cnt, 1024);
  if(C==0){
    ull lk=0;
    for(int n=tid;n<8192;n+=256){
      if(!mask_at(mask, b*8192+n, mode)){
        ull key = (((ull)__float_as_uint(al[n]))<<32) | (ull)(0x7FFFFFFFu - n);
        if(key>lk) lk=key;
      }
    }
    #pragma unroll
    for(int o=16;o;o>>=1){ ull k2v=__shfl_xor_sync(FULLMASK,lk,o); if(k2v>lk)lk=k2v; }
    if(lane==0) red8[warp]=lk;
    __syncthreads();
    if(tid==0){
      ull best=red8[0];
      #pragma unroll
      for(int w2=1;w2<8;w2++) if(red8[w2]>best) best=red8[w2];
      int idx = best ? (0x7FFFFFFF - (int)(best & 0xFFFFFFFFull)) : 0;
      g_sel[bt*64+0]=idx; g_w[bt*64+0]=1.f; g_cnt[bt]=1;
    }
    return;
  }
  {
    ull my[4]; int nm=0;
    for(int i=tid;i<C;i+=256){ my[nm]=cand[i]; nm++; }
    int cgt[4]={0,0,0,0};
    for(int j=0;j<C;j++){
      ull kj = cand[j];
      #pragma unroll
      for(int u=0;u<4;u++) if(u<nm && kj>my[u]) cgt[u]++;
    }
    #pragma unroll
    for(int u=0;u<4;u++){
      if(u<nm && cgt[u]<64){
        sval[cgt[u]] = __uint_as_float((unsigned)(my[u]>>32));
        sidx[cgt[u]] = 0x7FFFFFFF - (int)(my[u]&0xFFFFFFFFull);
      }
    }
  }
  __syncthreads();
  int S = min(C,64);
  if(tid<32){
    float s=0.f;
    for(int i=lane;i<S;i+=32) s+=sval[i];
    s=wredsum(s);
    if(lane==0) swsum=s;
  }
  __syncthreads();
  float iw = 1.f/fmaxf(swsum, 1e-8f);
  if(tid<S){
    g_sel[bt*64+tid]=sidx[tid];
    g_w[bt*64+tid]=sval[tid]*iw;
  }
  if(tid==0) g_cnt[bt]=S;
}

// ---------------- K7: gather + pool + wv matvec (64 blocks x 256) ----------------
__global__ void k7(const float* tokens, const float* W, const float* bias,
                   const float* preg, const float* preb, float* out){
  __shared__ float zsh[8][512];
  __shared__ float z[512];
  int bt=blockIdx.x, b=bt>>2;
  int tid=threadIdx.x, warp=tid>>5, lane=tid&31;
  int S = g_cnt[bt];
  float zacc[16];
  #pragma unroll
  for(int i=0;i<16;i++) zacc[i]=0.f;
  for(int k=warp;k<S;k+=8){
    int idx = g_sel[bt*64+k];
    float wk = g_w[bt*64+k];
    const float4* row = (const float4*)(tokens + ((size_t)b*8192+idx)*512);
    float4 x[4]; float s=0.f, ss=0.f;
    #pragma unroll
    for(int j=0;j<4;j++){
      x[j]=row[lane+32*j];
      s += x[j].x+x[j].y+x[j].z+x[j].w;
      ss += x[j].x*x[j].x+x[j].y*x[j].y+x[j].z*x[j].z+x[j].w*x[j].w;
    }
    s=wredsum(s); ss=wredsum(ss);
    float m=s*(1.f/512.f);
    float rstd=rsqrtf(ss*(1.f/512.f)-m*m+1e-5f);
    #pragma unroll
    for(int j=0;j<4;j++){
      int d0=(lane+32*j)*4;
      float v[4]={x[j].x,x[j].y,x[j].z,x[j].w};
      #pragma unroll
      for(int c=0;c<4;c++){
        int d=d0+c;
        zacc[j*4+c] += wk*((v[c]-m)*rstd*preg[d]+preb[d]);
      }
    }
  }
  #pragma unroll
  for(int j=0;j<4;j++)
    #pragma unroll
    for(int c=0;c<4;c++)
      zsh[warp][(lane+32*j)*4+c]=zacc[j*4+c];
  __syncthreads();
  #pragma unroll
  for(int rep=0;rep<2;rep++){
    int d = tid+rep*256;
    float a=0.f;
    #pragma unroll
    for(int w2=0;w2<8;w2++) a+=zsh[w2][d];
    z[d]=a;
  }
  __syncthreads();
  const float4* z4=(const float4*)z;
  for(int o=warp;o<512;o+=8){
    const float4* wr=(const float4*)(W+(size_t)(1024+o)*512);
    float a=0.f;
    #pragma unroll
    for(int j=0;j<4;j++){
      float4 A=z4[lane+32*j], B=wr[lane+32*j];
      a += A.x*B.x+A.y*B.y+A.z*B.z+A.w*B.w;
    }
    a=wredsum(a);
    if(lane==0) out[(size_t)bt*512+o]=a+bias[1024+o];
  }
}

// ---------------- launch ----------------
extern "C" void kernel_launch(void* const* d_in, const int* in_sizes, int n_in,
                              void* d_out, int out_size) {
  const float* tokens = (const float*)d_in[0];
  const void*  mask   = d_in[1];
  const float* q      = (const float*)d_in[2];
  const float* W      = (const float*)d_in[3];
  const float* bias   = (const float*)d_in[4];
  const float* preg   = (const float*)d_in[5];
  const float* preb   = (const float*)d_in[6];
  const float* qg     = (const float*)d_in[7];
  const float* qb     = (const float*)d_in[8];
  const float* logtau = (const float*)d_in[9];
  float* out = (float*)d_out;

  const int K3_SMEM = (16384 + 9216 + 32 + 4) * 4;   // 102544 B
  static int attr_done = 0;
  if(!attr_done){
    cudaFuncSetAttribute(k3, cudaFuncAttributeMaxDynamicSharedMemorySize, K3_SMEM);
    attr_done = 1;
  }

  k1f<<<65,256>>>(q, qg, qb, logtau, W, bias, (const unsigned char*)mask);
  k2<<<8,512>>>(W, preg);
  k3<<<296,256,K3_SMEM>>>(tokens, mask);
  k5<<<1024,256>>>(mask);
  k6<<<64,256>>>(mask);
  k7<<<64,256>>>(tokens, W, bias, preg, preb, out);
}